// round 1
// baseline (speedup 1.0000x reference)
#include <cuda_runtime.h>

#define BB 4
#define SS 4096
#define DE 768
#define DH 64

// Scratch for projected Q, K, V (4 MB each) — device globals, no allocation.
__device__ float g_q[BB * SS * DH];
__device__ float g_k[BB * SS * DH];
__device__ float g_v[BB * SS * DH];

// XOR swizzle in float4 granularity for 64-wide (16 float4) and 32-wide (8 float4) rows.
// Makes row-strided float4 LDS reads (r = tx*4+j varying across lanes) conflict-free-ish:
// bank group = (f ^ ((r>>2)&7)) mod 8 -> 8 distinct groups across tx.
__device__ __forceinline__ int swz16(int r, int f) { return r * 16 + (f ^ ((r >> 2) & 7)); }
__device__ __forceinline__ int swz8 (int r, int f) { return r * 8  + (f ^ ((r >> 2) & 7)); }

// ---------------------------------------------------------------------------
// QKV projection: C[M=16384, 64] = X[M,768] @ W[768,64] + bias
// grid (M/64, 1, 3) — z selects Q/K/V. 256 threads, 4x4 micro-tile, BK=32.
// ---------------------------------------------------------------------------
__global__ __launch_bounds__(256) void qkv_kernel(
    const float* __restrict__ X,
    const float* __restrict__ Wq, const float* __restrict__ bq,
    const float* __restrict__ Wk, const float* __restrict__ bk,
    const float* __restrict__ Wv, const float* __restrict__ bv)
{
    const float* W; const float* bias; float* C;
    if (blockIdx.z == 0)      { W = Wq; bias = bq; C = g_q; }
    else if (blockIdx.z == 1) { W = Wk; bias = bk; C = g_k; }
    else                      { W = Wv; bias = bv; C = g_v; }

    __shared__ float Xs[64 * 32];      // [m][k] plain (reads are ty-broadcast)
    __shared__ float Wt[64 * 32];      // [n][k] swizzled (8 float4 per row)

    const int tid = threadIdx.x;
    const int tx = tid & 15, ty = tid >> 4;
    const int m0 = blockIdx.x * 64;

    float acc[4][4];
    #pragma unroll
    for (int i = 0; i < 4; i++)
        #pragma unroll
        for (int j = 0; j < 4; j++) acc[i][j] = 0.f;

    for (int k0 = 0; k0 < DE; k0 += 32) {
        // X tile: 64 rows x 32 k  (coalesced, conflict-free stores)
        #pragma unroll
        for (int t = 0; t < 8; t++) {
            int idx = tid + t * 256;
            int r = idx >> 5, c = idx & 31;
            Xs[r * 32 + c] = X[(m0 + r) * DE + (k0 + c)];
        }
        // W tile: 32 k x 64 n -> store transposed+swizzled as [n][k]
        #pragma unroll
        for (int t = 0; t < 8; t++) {
            int idx = tid + t * 256;
            int r = idx >> 6, c = idx & 63;          // r: k in tile, c: n
            float v = W[(k0 + r) * DH + c];
            Wt[swz8(c, r >> 2) * 4 + (r & 3)] = v;
        }
        __syncthreads();

        const float4* X4 = (const float4*)Xs;
        const float4* W4 = (const float4*)Wt;
        #pragma unroll
        for (int f = 0; f < 8; f++) {
            float4 a[4], b[4];
            #pragma unroll
            for (int i = 0; i < 4; i++) a[i] = X4[(ty * 4 + i) * 8 + f];
            #pragma unroll
            for (int j = 0; j < 4; j++) b[j] = W4[swz8(tx * 4 + j, f)];
            #pragma unroll
            for (int i = 0; i < 4; i++)
                #pragma unroll
                for (int j = 0; j < 4; j++)
                    acc[i][j] += a[i].x * b[j].x + a[i].y * b[j].y
                               + a[i].z * b[j].z + a[i].w * b[j].w;
        }
        __syncthreads();
    }

    #pragma unroll
    for (int i = 0; i < 4; i++) {
        int m = m0 + ty * 4 + i;
        float4 o;
        o.x = acc[i][0] + bias[tx * 4 + 0];
        o.y = acc[i][1] + bias[tx * 4 + 1];
        o.z = acc[i][2] + bias[tx * 4 + 2];
        o.w = acc[i][3] + bias[tx * 4 + 3];
        *(float4*)&C[m * DH + tx * 4] = o;
    }
}

// ---------------------------------------------------------------------------
// Flash attention: grid (S/64, B), 256 threads, 64-query block, 64-key tiles.
// Online softmax with additive key mask (-1e9). All fp32.
// ---------------------------------------------------------------------------
__global__ __launch_bounds__(256) void attn_kernel(const int* __restrict__ mask,
                                                   float* __restrict__ out)
{
    extern __shared__ float sm[];
    float* Qs  = sm;            // 64x64 plain, pre-scaled by 1/sqrt(Dh)
    float* Ks  = Qs + 4096;     // 64x64 swizzled [key][d]
    float* Vt  = Ks + 4096;     // 64x64 swizzled [d][key]
    float* Ps  = Vt + 4096;     // 64x64 swizzled [q][key]
    float* msk = Ps + 4096;     // 64 additive mask values

    const int tid = threadIdx.x;
    const int tx = tid & 15, ty = tid >> 4;
    const int b  = blockIdx.y;
    const int q0 = blockIdx.x * 64;

    // Load Q tile (scaled)
    #pragma unroll
    for (int t = 0; t < 16; t++) {
        int idx = tid + t * 256;
        int r = idx >> 6, d = idx & 63;
        Qs[r * 64 + d] = g_q[(b * SS + q0 + r) * DH + d] * 0.125f;
    }

    float m_i[4], l_i[4], o[4][4];
    #pragma unroll
    for (int i = 0; i < 4; i++) {
        m_i[i] = -1e30f; l_i[i] = 0.f;
        #pragma unroll
        for (int j = 0; j < 4; j++) o[i][j] = 0.f;
    }

    for (int kt = 0; kt < SS / 64; kt++) {
        const int key0 = kt * 64;
        #pragma unroll
        for (int t = 0; t < 16; t++) {
            int idx = tid + t * 256;
            int r = idx >> 6, d = idx & 63;
            float kv = g_k[(b * SS + key0 + r) * DH + d];
            float vv = g_v[(b * SS + key0 + r) * DH + d];
            Ks[swz16(r, d >> 2) * 4 + (d & 3)] = kv;
            Vt[swz16(d, r >> 2) * 4 + (r & 3)] = vv;
        }
        if (tid < 64)
            msk[tid] = (mask[b * SS + key0 + tid] == 0) ? -1e9f : 0.f;
        __syncthreads();

        // ---- S = Q K^T (this thread: rows ty*4.., cols tx*4..) ----
        float s[4][4];
        #pragma unroll
        for (int i = 0; i < 4; i++)
            #pragma unroll
            for (int j = 0; j < 4; j++) s[i][j] = 0.f;

        const float4* Q4 = (const float4*)Qs;
        const float4* K4 = (const float4*)Ks;
        #pragma unroll
        for (int f = 0; f < 16; f++) {
            float4 a[4], bb[4];
            #pragma unroll
            for (int i = 0; i < 4; i++) a[i]  = Q4[(ty * 4 + i) * 16 + f];
            #pragma unroll
            for (int j = 0; j < 4; j++) bb[j] = K4[swz16(tx * 4 + j, f)];
            #pragma unroll
            for (int i = 0; i < 4; i++)
                #pragma unroll
                for (int j = 0; j < 4; j++)
                    s[i][j] += a[i].x * bb[j].x + a[i].y * bb[j].y
                             + a[i].z * bb[j].z + a[i].w * bb[j].w;
        }

        // additive mask
        #pragma unroll
        for (int j = 0; j < 4; j++) {
            float mj = msk[tx * 4 + j];
            #pragma unroll
            for (int i = 0; i < 4; i++) s[i][j] += mj;
        }

        // ---- online softmax (row groups = 16 lanes sharing ty) ----
        float4* P4 = (float4*)Ps;
        #pragma unroll
        for (int i = 0; i < 4; i++) {
            float tm = fmaxf(fmaxf(s[i][0], s[i][1]), fmaxf(s[i][2], s[i][3]));
            #pragma unroll
            for (int off = 8; off; off >>= 1)
                tm = fmaxf(tm, __shfl_xor_sync(0xffffffffu, tm, off));
            float mn = fmaxf(m_i[i], tm);
            float corr = __expf(m_i[i] - mn);
            m_i[i] = mn;
            float rl = 0.f;
            #pragma unroll
            for (int j = 0; j < 4; j++) {
                float p = __expf(s[i][j] - mn);
                s[i][j] = p;
                rl += p;
            }
            #pragma unroll
            for (int off = 8; off; off >>= 1)
                rl += __shfl_xor_sync(0xffffffffu, rl, off);
            l_i[i] = l_i[i] * corr + rl;
            #pragma unroll
            for (int j = 0; j < 4; j++) o[i][j] *= corr;
            P4[swz16(ty * 4 + i, tx)] = make_float4(s[i][0], s[i][1], s[i][2], s[i][3]);
        }
        __syncthreads();

        // ---- O += P V : o[i][j] += sum_c P[q][c] * V[c][d] (V stored d-major) ----
        const float4* Pc = (const float4*)Ps;
        const float4* Vc = (const float4*)Vt;
        #pragma unroll
        for (int f = 0; f < 16; f++) {
            float4 p[4], v[4];
            #pragma unroll
            for (int i = 0; i < 4; i++) p[i] = Pc[swz16(ty * 4 + i, f)];
            #pragma unroll
            for (int j = 0; j < 4; j++) v[j] = Vc[swz16(tx * 4 + j, f)];
            #pragma unroll
            for (int i = 0; i < 4; i++)
                #pragma unroll
                for (int j = 0; j < 4; j++)
                    o[i][j] += p[i].x * v[j].x + p[i].y * v[j].y
                             + p[i].z * v[j].z + p[i].w * v[j].w;
        }
        __syncthreads();   // before next tile overwrites Ks/Vt/Ps
    }

    #pragma unroll
    for (int i = 0; i < 4; i++) {
        float inv = 1.f / l_i[i];
        float4 r4 = make_float4(o[i][0] * inv, o[i][1] * inv,
                                o[i][2] * inv, o[i][3] * inv);
        *(float4*)&out[(b * SS + q0 + ty * 4 + i) * DH + tx * 4] = r4;
    }
}

// ---------------------------------------------------------------------------
extern "C" void kernel_launch(void* const* d_in, const int* in_sizes, int n_in,
                              void* d_out, int out_size)
{
    const float* x  = (const float*)d_in[0];
    const int* mask = (const int*)d_in[1];
    const float* Wq = (const float*)d_in[2];
    const float* bq = (const float*)d_in[3];
    const float* Wk = (const float*)d_in[4];
    const float* bk = (const float*)d_in[5];
    const float* Wv = (const float*)d_in[6];
    const float* bv = (const float*)d_in[7];
    float* out = (float*)d_out;

    dim3 g1(BB * SS / 64, 1, 3);
    qkv_kernel<<<g1, 256>>>(x, Wq, bq, Wk, bk, Wv, bv);

    const int smem = (4 * 64 * 64 + 64) * (int)sizeof(float);   // 65792 B
    cudaFuncSetAttribute(attn_kernel,
                         cudaFuncAttributeMaxDynamicSharedMemorySize, smem);
    dim3 g2(SS / 64, BB);
    attn_kernel<<<g2, 256, smem>>>(mask, out);
}

// round 3
// speedup vs baseline: 4.6218x; 4.6218x over previous
#include <cuda_runtime.h>
#include <cstdint>

#define BB 4
#define SS 4096
#define DE 768
#define DH 64
#define QT 128
#define KT 128

// Scratch for projected Q, K, V — device globals, no allocation.
__device__ float g_q[BB * SS * DH];
__device__ float g_k[BB * SS * DH];
__device__ float g_v[BB * SS * DH];

// ---------------------------------------------------------------------------
// helpers
// ---------------------------------------------------------------------------
__device__ __forceinline__ uint32_t f2tf32(float x) {
    uint32_t r;
    asm("cvt.rna.tf32.f32 %0, %1;" : "=r"(r) : "f"(x));
    return r;
}
__device__ __forceinline__ float ex2f(float x) {
    float y; asm("ex2.approx.f32 %0, %1;" : "=f"(y) : "f"(x)); return y;
}
// D += A(16x8) * B(8x8), tf32
__device__ __forceinline__ void mma8(float* d, const uint32_t* a, const uint32_t* b) {
    asm volatile(
        "mma.sync.aligned.m16n8k8.row.col.f32.tf32.tf32.f32 "
        "{%0,%1,%2,%3}, {%4,%5,%6,%7}, {%8,%9}, {%0,%1,%2,%3};"
        : "+f"(d[0]), "+f"(d[1]), "+f"(d[2]), "+f"(d[3])
        : "r"(a[0]), "r"(a[1]), "r"(a[2]), "r"(a[3]), "r"(b[0]), "r"(b[1]));
}

// ===========================================================================
// Fused QKV projection via tf32 mma.sync.
// C[16384, 192] = X[16384,768] @ [Wq|Wk|Wv] + [bq|bk|bv]
// grid: 128 CTAs (128 rows each), 256 threads = 8 warps (4m x 2n).
// ===========================================================================
#define XS_STR 36
#define WS_STR 200

__global__ __launch_bounds__(256) void qkv_mma(
    const float* __restrict__ X,
    const float* __restrict__ Wq, const float* __restrict__ bq,
    const float* __restrict__ Wk, const float* __restrict__ bk,
    const float* __restrict__ Wv, const float* __restrict__ bv)
{
    __shared__ float Xs[128 * XS_STR];
    __shared__ float Ws[32 * WS_STR];
    __shared__ float bsm[192];

    const int tid = threadIdx.x;
    const int wid = tid >> 5, lane = tid & 31;
    const int g = lane >> 2, tg = lane & 3;
    const int warp_m = wid & 3, warp_n = wid >> 2;
    const int r0 = warp_m * 32;          // warp's row base in tile
    const int n0 = warp_n * 96;          // warp's col base (of 192)
    const int m0 = blockIdx.x * 128;

    if (tid < 192) {
        float bv_ = (tid < 64) ? bq[tid] : (tid < 128) ? bk[tid - 64] : bv[tid - 128];
        bsm[tid] = bv_;
    }

    float acc[2][12][4];
    #pragma unroll
    for (int m = 0; m < 2; m++)
        #pragma unroll
        for (int n = 0; n < 12; n++)
            #pragma unroll
            for (int i = 0; i < 4; i++) acc[m][n][i] = 0.f;

    for (int k0 = 0; k0 < DE; k0 += 32) {
        // X tile 128x32 -> Xs (tf32)
        #pragma unroll
        for (int i = 0; i < 4; i++) {
            int idx = tid + i * 256;
            int r = idx >> 3, c4 = (idx & 7) * 4;
            float4 v = *(const float4*)&X[(size_t)(m0 + r) * DE + k0 + c4];
            uint4 u = make_uint4(f2tf32(v.x), f2tf32(v.y), f2tf32(v.z), f2tf32(v.w));
            *(uint4*)&Xs[r * XS_STR + c4] = u;
        }
        // W tiles 32x64 each -> Ws cols [0|64|128]
        #pragma unroll
        for (int mtx = 0; mtx < 3; mtx++) {
            const float* W = (mtx == 0) ? Wq : (mtx == 1) ? Wk : Wv;
            #pragma unroll
            for (int i = 0; i < 2; i++) {
                int idx = tid + i * 256;
                int kr = idx >> 4, c4 = (idx & 15) * 4;
                float4 v = *(const float4*)&W[(size_t)(k0 + kr) * DH + c4];
                uint4 u = make_uint4(f2tf32(v.x), f2tf32(v.y), f2tf32(v.z), f2tf32(v.w));
                *(uint4*)&Ws[kr * WS_STR + mtx * 64 + c4] = u;
            }
        }
        __syncthreads();

        #pragma unroll
        for (int kf = 0; kf < 4; kf++) {
            uint32_t a[2][4];
            #pragma unroll
            for (int m = 0; m < 2; m++) {
                int r = r0 + m * 16 + g;
                a[m][0] = __float_as_uint(Xs[r * XS_STR + kf * 8 + tg]);
                a[m][1] = __float_as_uint(Xs[(r + 8) * XS_STR + kf * 8 + tg]);
                a[m][2] = __float_as_uint(Xs[r * XS_STR + kf * 8 + tg + 4]);
                a[m][3] = __float_as_uint(Xs[(r + 8) * XS_STR + kf * 8 + tg + 4]);
            }
            #pragma unroll
            for (int nf = 0; nf < 12; nf++) {
                uint32_t b[2];
                b[0] = __float_as_uint(Ws[(kf * 8 + tg) * WS_STR + n0 + nf * 8 + g]);
                b[1] = __float_as_uint(Ws[(kf * 8 + tg + 4) * WS_STR + n0 + nf * 8 + g]);
                mma8(acc[0][nf], a[0], b);
                mma8(acc[1][nf], a[1], b);
            }
        }
        __syncthreads();
    }

    // epilogue: bias + scatter to g_q / g_k / g_v
    #pragma unroll
    for (int m = 0; m < 2; m++) {
        #pragma unroll
        for (int nf = 0; nf < 12; nf++) {
            int col = n0 + nf * 8 + 2 * tg;
            int mtx = col >> 6, cc = col & 63;
            float* C = (mtx == 0) ? g_q : (mtx == 1) ? g_k : g_v;
            float b0 = bsm[col], b1 = bsm[col + 1];
            int ra = m0 + r0 + m * 16 + g;
            float2 v0 = make_float2(acc[m][nf][0] + b0, acc[m][nf][1] + b1);
            float2 v1 = make_float2(acc[m][nf][2] + b0, acc[m][nf][3] + b1);
            *(float2*)&C[(size_t)ra * DH + cc] = v0;
            *(float2*)&C[(size_t)(ra + 8) * DH + cc] = v1;
        }
    }
}

// ===========================================================================
// Attention via tf32 mma.sync, no online rescale (bounded scores).
// grid (SS/128, BB), 256 threads = 8 warps (4m x 2n).
// ===========================================================================
#define SS_STR 132
#define KV_STR 72

__global__ __launch_bounds__(256, 1) void attn_mma(const int* __restrict__ mask,
                                                   float* __restrict__ out)
{
    extern __shared__ float sm[];
    float* Ssm  = sm;                        // 128 x 132  (S / P, also Q staging)
    float* Ks   = Ssm + 128 * SS_STR;        // 128 x 72
    float* Vs   = Ks + 128 * KV_STR;         // 128 x 72
    float* mskf = Vs + 128 * KV_STR;         // 128
    float* lsum = mskf + 128;                // 2 x 128
    float* ltot = lsum + 256;                // 128

    const int tid = threadIdx.x;
    const int wid = tid >> 5, lane = tid & 31;
    const int g = lane >> 2, tg = lane & 3;
    const int warp_m = wid & 3, warp_n = wid >> 2;
    const int r0 = warp_m * 32;
    const int n0 = warp_n * 64;     // S col base
    const int n0v = warp_n * 32;    // O col base
    const int b = blockIdx.y;
    const int q0 = blockIdx.x * QT;

    // stage Q (scaled by log2(e)/8, tf32) into Ssm, read fragments, keep in regs
    const float SCL = 0.18033688011112042f;
    #pragma unroll
    for (int i = 0; i < 8; i++) {
        int idx = tid + i * 256;
        int r = idx >> 4, c4 = (idx & 15) * 4;
        float4 v = *(const float4*)&g_q[(size_t)(b * SS + q0 + r) * DH + c4];
        uint4 u = make_uint4(f2tf32(v.x * SCL), f2tf32(v.y * SCL),
                             f2tf32(v.z * SCL), f2tf32(v.w * SCL));
        *(uint4*)&Ssm[r * SS_STR + c4] = u;
    }
    if (tid < 128) ltot[tid] = 0.f;
    __syncthreads();

    uint32_t qa[2][8][4];
    #pragma unroll
    for (int m = 0; m < 2; m++) {
        int r = r0 + m * 16 + g;
        #pragma unroll
        for (int kf = 0; kf < 8; kf++) {
            qa[m][kf][0] = __float_as_uint(Ssm[r * SS_STR + kf * 8 + tg]);
            qa[m][kf][1] = __float_as_uint(Ssm[(r + 8) * SS_STR + kf * 8 + tg]);
            qa[m][kf][2] = __float_as_uint(Ssm[r * SS_STR + kf * 8 + tg + 4]);
            qa[m][kf][3] = __float_as_uint(Ssm[(r + 8) * SS_STR + kf * 8 + tg + 4]);
        }
    }
    __syncthreads();

    float oacc[2][4][4];
    #pragma unroll
    for (int m = 0; m < 2; m++)
        #pragma unroll
        for (int n = 0; n < 4; n++)
            #pragma unroll
            for (int i = 0; i < 4; i++) oacc[m][n][i] = 0.f;

    for (int kt = 0; kt < SS / KT; kt++) {
        const int k0 = kt * KT;
        // load K, V tiles (tf32-rounded)
        #pragma unroll
        for (int i = 0; i < 8; i++) {
            int idx = tid + i * 256;
            int r = idx >> 4, c4 = (idx & 15) * 4;
            float4 kv = *(const float4*)&g_k[(size_t)(b * SS + k0 + r) * DH + c4];
            float4 vv = *(const float4*)&g_v[(size_t)(b * SS + k0 + r) * DH + c4];
            *(uint4*)&Ks[r * KV_STR + c4] =
                make_uint4(f2tf32(kv.x), f2tf32(kv.y), f2tf32(kv.z), f2tf32(kv.w));
            *(uint4*)&Vs[r * KV_STR + c4] =
                make_uint4(f2tf32(vv.x), f2tf32(vv.y), f2tf32(vv.z), f2tf32(vv.w));
        }
        if (tid < 128)
            mskf[tid] = (mask[b * SS + k0 + tid] != 0) ? 1.f : 0.f;
        __syncthreads();

        // ---- S = Q K^T ----
        float sacc[2][8][4];
        #pragma unroll
        for (int m = 0; m < 2; m++)
            #pragma unroll
            for (int n = 0; n < 8; n++)
                #pragma unroll
                for (int i = 0; i < 4; i++) sacc[m][n][i] = 0.f;

        #pragma unroll
        for (int kf = 0; kf < 8; kf++) {
            #pragma unroll
            for (int nf = 0; nf < 8; nf++) {
                uint32_t bfr[2];
                bfr[0] = __float_as_uint(Ks[(n0 + nf * 8 + g) * KV_STR + kf * 8 + tg]);
                bfr[1] = __float_as_uint(Ks[(n0 + nf * 8 + g) * KV_STR + kf * 8 + tg + 4]);
                mma8(sacc[0][nf], qa[0][kf], bfr);
                mma8(sacc[1][nf], qa[1][kf], bfr);
            }
        }

        // ---- softmax in registers: p = exp2(s) * mask ----
        float rs[2][2] = {{0.f, 0.f}, {0.f, 0.f}};
        #pragma unroll
        for (int m = 0; m < 2; m++) {
            int rbase = r0 + m * 16 + g;
            #pragma unroll
            for (int nf = 0; nf < 8; nf++) {
                int c = n0 + nf * 8 + 2 * tg;
                float mk0 = mskf[c], mk1 = mskf[c + 1];
                float p0 = ex2f(sacc[m][nf][0]) * mk0;
                float p1 = ex2f(sacc[m][nf][1]) * mk1;
                float p2 = ex2f(sacc[m][nf][2]) * mk0;
                float p3 = ex2f(sacc[m][nf][3]) * mk1;
                rs[m][0] += p0 + p1;
                rs[m][1] += p2 + p3;
                // tf32-round and store P to SMEM (own region)
                float2 w0 = make_float2(__uint_as_float(f2tf32(p0)),
                                        __uint_as_float(f2tf32(p1)));
                float2 w1 = make_float2(__uint_as_float(f2tf32(p2)),
                                        __uint_as_float(f2tf32(p3)));
                *(float2*)&Ssm[rbase * SS_STR + c] = w0;
                *(float2*)&Ssm[(rbase + 8) * SS_STR + c] = w1;
            }
        }
        // reduce row sums across the 4 tg lanes
        #pragma unroll
        for (int m = 0; m < 2; m++) {
            #pragma unroll
            for (int h = 0; h < 2; h++) {
                float v = rs[m][h];
                v += __shfl_xor_sync(0xffffffffu, v, 1);
                v += __shfl_xor_sync(0xffffffffu, v, 2);
                rs[m][h] = v;
            }
            if (tg == 0) {
                lsum[warp_n * 128 + r0 + m * 16 + g] = rs[m][0];
                lsum[warp_n * 128 + r0 + m * 16 + 8 + g] = rs[m][1];
            }
        }
        __syncthreads();
        if (tid < 128) ltot[tid] += lsum[tid] + lsum[128 + tid];

        // ---- O += P V ----
        #pragma unroll
        for (int kf = 0; kf < 16; kf++) {
            uint32_t pa[2][4];
            #pragma unroll
            for (int m = 0; m < 2; m++) {
                int r = r0 + m * 16 + g;
                pa[m][0] = __float_as_uint(Ssm[r * SS_STR + kf * 8 + tg]);
                pa[m][1] = __float_as_uint(Ssm[(r + 8) * SS_STR + kf * 8 + tg]);
                pa[m][2] = __float_as_uint(Ssm[r * SS_STR + kf * 8 + tg + 4]);
                pa[m][3] = __float_as_uint(Ssm[(r + 8) * SS_STR + kf * 8 + tg + 4]);
            }
            #pragma unroll
            for (int nf = 0; nf < 4; nf++) {
                uint32_t bfr[2];
                bfr[0] = __float_as_uint(Vs[(kf * 8 + tg) * KV_STR + n0v + nf * 8 + g]);
                bfr[1] = __float_as_uint(Vs[(kf * 8 + tg + 4) * KV_STR + n0v + nf * 8 + g]);
                mma8(oacc[0][nf], pa[0], bfr);
                mma8(oacc[1][nf], pa[1], bfr);
            }
        }
        __syncthreads();   // protect Ks/Vs/Ssm before next tile
    }

    // epilogue: normalize by row sums
    #pragma unroll
    for (int m = 0; m < 2; m++) {
        int ra = r0 + m * 16 + g;
        float li0 = 1.f / ltot[ra];
        float li1 = 1.f / ltot[ra + 8];
        #pragma unroll
        for (int nf = 0; nf < 4; nf++) {
            int c = n0v + nf * 8 + 2 * tg;
            float2 v0 = make_float2(oacc[m][nf][0] * li0, oacc[m][nf][1] * li0);
            float2 v1 = make_float2(oacc[m][nf][2] * li1, oacc[m][nf][3] * li1);
            *(float2*)&out[(size_t)(b * SS + q0 + ra) * DH + c] = v0;
            *(float2*)&out[(size_t)(b * SS + q0 + ra + 8) * DH + c] = v1;
        }
    }
}

// ===========================================================================
extern "C" void kernel_launch(void* const* d_in, const int* in_sizes, int n_in,
                              void* d_out, int out_size)
{
    const float* x  = (const float*)d_in[0];
    const int* mask = (const int*)d_in[1];
    const float* Wq = (const float*)d_in[2];
    const float* bq = (const float*)d_in[3];
    const float* Wk = (const float*)d_in[4];
    const float* bk = (const float*)d_in[5];
    const float* Wv = (const float*)d_in[6];
    const float* bv = (const float*)d_in[7];
    float* out = (float*)d_out;

    qkv_mma<<<BB * SS / 128, 256>>>(x, Wq, bq, Wk, bk, Wv, bv);

    const int smem = (128 * SS_STR + 2 * 128 * KV_STR + 128 + 256 + 128) * (int)sizeof(float);
    cudaFuncSetAttribute(attn_mma, cudaFuncAttributeMaxDynamicSharedMemorySize, smem);
    dim3 g2(SS / QT, BB);
    attn_mma<<<g2, 256, smem>>>(mask, out);
}

// round 4
// speedup vs baseline: 6.7276x; 1.4556x over previous
#include <cuda_runtime.h>
#include <cuda_fp16.h>
#include <cstdint>

#define BB 4
#define SS 4096
#define DE 768
#define DH 64
#define QT 128
#define KT 128

// Scratch for projected Q, K, V — device globals, no allocation.
__device__ float g_q[BB * SS * DH];
__device__ float g_k[BB * SS * DH];
__device__ float g_v[BB * SS * DH];

// ---------------------------------------------------------------------------
// helpers
// ---------------------------------------------------------------------------
__device__ __forceinline__ uint32_t f2tf32(float x) {
    uint32_t r;
    asm("cvt.rna.tf32.f32 %0, %1;" : "=r"(r) : "f"(x));
    return r;
}
__device__ __forceinline__ float ex2f(float x) {
    float y; asm("ex2.approx.f32 %0, %1;" : "=f"(y) : "f"(x)); return y;
}
// tf32: D += A(16x8) * B(8x8)
__device__ __forceinline__ void mma8(float* d, const uint32_t* a, const uint32_t* b) {
    asm volatile(
        "mma.sync.aligned.m16n8k8.row.col.f32.tf32.tf32.f32 "
        "{%0,%1,%2,%3}, {%4,%5,%6,%7}, {%8,%9}, {%0,%1,%2,%3};"
        : "+f"(d[0]), "+f"(d[1]), "+f"(d[2]), "+f"(d[3])
        : "r"(a[0]), "r"(a[1]), "r"(a[2]), "r"(a[3]), "r"(b[0]), "r"(b[1]));
}
// fp16: D += A(16x16) * B(16x8), fp32 accum
__device__ __forceinline__ void mma16(float* d, const uint32_t* a, uint32_t b0, uint32_t b1) {
    asm volatile(
        "mma.sync.aligned.m16n8k16.row.col.f32.f16.f16.f32 "
        "{%0,%1,%2,%3}, {%4,%5,%6,%7}, {%8,%9}, {%0,%1,%2,%3};"
        : "+f"(d[0]), "+f"(d[1]), "+f"(d[2]), "+f"(d[3])
        : "r"(a[0]), "r"(a[1]), "r"(a[2]), "r"(a[3]), "r"(b0), "r"(b1));
}
__device__ __forceinline__ void ldmx4(uint32_t* r, uint32_t addr) {
    asm volatile("ldmatrix.sync.aligned.m8n8.x4.shared.b16 {%0,%1,%2,%3}, [%4];"
        : "=r"(r[0]), "=r"(r[1]), "=r"(r[2]), "=r"(r[3]) : "r"(addr));
}
__device__ __forceinline__ void ldmx2(uint32_t& r0, uint32_t& r1, uint32_t addr) {
    asm volatile("ldmatrix.sync.aligned.m8n8.x2.shared.b16 {%0,%1}, [%2];"
        : "=r"(r0), "=r"(r1) : "r"(addr));
}
__device__ __forceinline__ void ldmx2t(uint32_t& r0, uint32_t& r1, uint32_t addr) {
    asm volatile("ldmatrix.sync.aligned.m8n8.x2.trans.shared.b16 {%0,%1}, [%2];"
        : "=r"(r0), "=r"(r1) : "r"(addr));
}
__device__ __forceinline__ uint32_t packh2(float lo, float hi) {
    __half2 h = __floats2half2_rn(lo, hi);
    return *(uint32_t*)&h;
}

// ===========================================================================
// Fused QKV projection via tf32 mma.sync (unchanged from R3, known good).
// ===========================================================================
#define XS_STR 36
#define WS_STR 200

__global__ __launch_bounds__(256) void qkv_mma(
    const float* __restrict__ X,
    const float* __restrict__ Wq, const float* __restrict__ bq,
    const float* __restrict__ Wk, const float* __restrict__ bk,
    const float* __restrict__ Wv, const float* __restrict__ bv)
{
    __shared__ float Xs[128 * XS_STR];
    __shared__ float Ws[32 * WS_STR];
    __shared__ float bsm[192];

    const int tid = threadIdx.x;
    const int wid = tid >> 5, lane = tid & 31;
    const int g = lane >> 2, tg = lane & 3;
    const int warp_m = wid & 3, warp_n = wid >> 2;
    const int r0 = warp_m * 32;
    const int n0 = warp_n * 96;
    const int m0 = blockIdx.x * 128;

    if (tid < 192) {
        float bv_ = (tid < 64) ? bq[tid] : (tid < 128) ? bk[tid - 64] : bv[tid - 128];
        bsm[tid] = bv_;
    }

    float acc[2][12][4];
    #pragma unroll
    for (int m = 0; m < 2; m++)
        #pragma unroll
        for (int n = 0; n < 12; n++)
            #pragma unroll
            for (int i = 0; i < 4; i++) acc[m][n][i] = 0.f;

    for (int k0 = 0; k0 < DE; k0 += 32) {
        #pragma unroll
        for (int i = 0; i < 4; i++) {
            int idx = tid + i * 256;
            int r = idx >> 3, c4 = (idx & 7) * 4;
            float4 v = *(const float4*)&X[(size_t)(m0 + r) * DE + k0 + c4];
            uint4 u = make_uint4(f2tf32(v.x), f2tf32(v.y), f2tf32(v.z), f2tf32(v.w));
            *(uint4*)&Xs[r * XS_STR + c4] = u;
        }
        #pragma unroll
        for (int mtx = 0; mtx < 3; mtx++) {
            const float* W = (mtx == 0) ? Wq : (mtx == 1) ? Wk : Wv;
            #pragma unroll
            for (int i = 0; i < 2; i++) {
                int idx = tid + i * 256;
                int kr = idx >> 4, c4 = (idx & 15) * 4;
                float4 v = *(const float4*)&W[(size_t)(k0 + kr) * DH + c4];
                uint4 u = make_uint4(f2tf32(v.x), f2tf32(v.y), f2tf32(v.z), f2tf32(v.w));
                *(uint4*)&Ws[kr * WS_STR + mtx * 64 + c4] = u;
            }
        }
        __syncthreads();

        #pragma unroll
        for (int kf = 0; kf < 4; kf++) {
            uint32_t a[2][4];
            #pragma unroll
            for (int m = 0; m < 2; m++) {
                int r = r0 + m * 16 + g;
                a[m][0] = __float_as_uint(Xs[r * XS_STR + kf * 8 + tg]);
                a[m][1] = __float_as_uint(Xs[(r + 8) * XS_STR + kf * 8 + tg]);
                a[m][2] = __float_as_uint(Xs[r * XS_STR + kf * 8 + tg + 4]);
                a[m][3] = __float_as_uint(Xs[(r + 8) * XS_STR + kf * 8 + tg + 4]);
            }
            #pragma unroll
            for (int nf = 0; nf < 12; nf++) {
                uint32_t b[2];
                b[0] = __float_as_uint(Ws[(kf * 8 + tg) * WS_STR + n0 + nf * 8 + g]);
                b[1] = __float_as_uint(Ws[(kf * 8 + tg + 4) * WS_STR + n0 + nf * 8 + g]);
                mma8(acc[0][nf], a[0], b);
                mma8(acc[1][nf], a[1], b);
            }
        }
        __syncthreads();
    }

    #pragma unroll
    for (int m = 0; m < 2; m++) {
        #pragma unroll
        for (int nf = 0; nf < 12; nf++) {
            int col = n0 + nf * 8 + 2 * tg;
            int mtx = col >> 6, cc = col & 63;
            float* C = (mtx == 0) ? g_q : (mtx == 1) ? g_k : g_v;
            float b0 = bsm[col], b1 = bsm[col + 1];
            int ra = m0 + r0 + m * 16 + g;
            float2 v0 = make_float2(acc[m][nf][0] + b0, acc[m][nf][1] + b1);
            float2 v1 = make_float2(acc[m][nf][2] + b0, acc[m][nf][3] + b1);
            *(float2*)&C[(size_t)ra * DH + cc] = v0;
            *(float2*)&C[(size_t)(ra + 8) * DH + cc] = v1;
        }
    }
}

// ===========================================================================
// Attention: fp16 m16n8k16 mma + ldmatrix, P kept in registers.
// grid (SS/128, BB), 256 threads = 8 warps (warp_m = rows/32, warp_n = keys/64)
// ===========================================================================
#define KV_STRH 72          // half stride for K/V/Q smem tiles
#define OB_STR 72           // float stride for O combine buffer

__global__ __launch_bounds__(256, 1) void attn_mma(const int* __restrict__ mask,
                                                   float* __restrict__ out)
{
    extern __shared__ char smc[];
    __half* Ks   = (__half*)smc;                       // 128 x 72 half (18432 B)
    __half* Vs   = (__half*)(smc + 18432);             // 128 x 72 half
    float* mskf  = (float*)(smc + 36864);              // 128
    float* lsum  = mskf + 128;                         // 2 x 128
    float* ltot  = lsum + 256;                         // 128
    float* Obuf  = (float*)smc;                        // reuse after loop: 128 x 72 f32

    const int tid = threadIdx.x;
    const int wid = tid >> 5, lane = tid & 31;
    const int g = lane >> 2, tg = lane & 3;
    const int warp_m = wid & 3, warp_n = wid >> 2;
    const int r0 = warp_m * 32;
    const int n0 = warp_n * 64;
    const int b = blockIdx.y;
    const int q0 = blockIdx.x * QT;

    // ---- stage Q (scaled by log2(e)/8) as fp16 into Ks region, build fragments
    const float SCL = 0.18033688011112042f;
    #pragma unroll
    for (int i = 0; i < 8; i++) {
        int idx = tid + i * 256;
        int r = idx >> 4, d4 = (idx & 15) * 4;
        float4 v = *(const float4*)&g_q[(size_t)(b * SS + q0 + r) * DH + d4];
        uint2 u;
        u.x = packh2(v.x * SCL, v.y * SCL);
        u.y = packh2(v.z * SCL, v.w * SCL);
        *(uint2*)&Ks[r * KV_STRH + d4] = u;
    }
    if (tid < 128) ltot[tid] = 0.f;
    __syncthreads();

    uint32_t qa[2][4][4];
    {
        uint32_t qbase = (uint32_t)__cvta_generic_to_shared(Ks);
        #pragma unroll
        for (int m = 0; m < 2; m++)
            #pragma unroll
            for (int s = 0; s < 4; s++) {
                uint32_t a = qbase +
                    ((uint32_t)((r0 + m * 16 + (lane & 15)) * KV_STRH + 16 * s + ((lane >> 4) * 8))) * 2u;
                ldmx4(qa[m][s], a);
            }
    }
    __syncthreads();

    float oacc[2][8][4];
    #pragma unroll
    for (int m = 0; m < 2; m++)
        #pragma unroll
        for (int n = 0; n < 8; n++)
            #pragma unroll
            for (int i = 0; i < 4; i++) oacc[m][n][i] = 0.f;

    const uint32_t kb_base = (uint32_t)__cvta_generic_to_shared(Ks);
    const uint32_t vb_base = (uint32_t)__cvta_generic_to_shared(Vs);

    for (int kt = 0; kt < SS / KT; kt++) {
        const int k0 = kt * KT;
        // ---- load K/V tiles as fp16 ----
        #pragma unroll
        for (int i = 0; i < 8; i++) {
            int idx = tid + i * 256;
            int r = idx >> 4, d4 = (idx & 15) * 4;
            float4 kv = *(const float4*)&g_k[(size_t)(b * SS + k0 + r) * DH + d4];
            float4 vv = *(const float4*)&g_v[(size_t)(b * SS + k0 + r) * DH + d4];
            uint2 uk, uv;
            uk.x = packh2(kv.x, kv.y); uk.y = packh2(kv.z, kv.w);
            uv.x = packh2(vv.x, vv.y); uv.y = packh2(vv.z, vv.w);
            *(uint2*)&Ks[r * KV_STRH + d4] = uk;
            *(uint2*)&Vs[r * KV_STRH + d4] = uv;
        }
        if (tid < 128)
            mskf[tid] = (mask[b * SS + k0 + tid] != 0) ? 1.f : 0.f;
        __syncthreads();

        // ---- S = Q K^T ----
        float sacc[2][8][4];
        #pragma unroll
        for (int m = 0; m < 2; m++)
            #pragma unroll
            for (int n = 0; n < 8; n++)
                #pragma unroll
                for (int i = 0; i < 4; i++) sacc[m][n][i] = 0.f;

        #pragma unroll
        for (int s = 0; s < 4; s++) {
            #pragma unroll
            for (int nf = 0; nf < 8; nf++) {
                uint32_t b0, b1;
                uint32_t a = kb_base +
                    ((uint32_t)((n0 + nf * 8 + (lane & 7)) * KV_STRH + 16 * s + (((lane >> 3) & 1) * 8))) * 2u;
                ldmx2(b0, b1, a);
                mma16(sacc[0][nf], qa[0][s], b0, b1);
                mma16(sacc[1][nf], qa[1][s], b0, b1);
            }
        }

        // ---- p = exp2(s) * mask, row sums; P stays in registers ----
        float rs[2][2] = {{0.f, 0.f}, {0.f, 0.f}};
        #pragma unroll
        for (int m = 0; m < 2; m++) {
            #pragma unroll
            for (int nf = 0; nf < 8; nf++) {
                int c = n0 + nf * 8 + 2 * tg;
                float mk0 = mskf[c], mk1 = mskf[c + 1];
                float p0 = ex2f(sacc[m][nf][0]) * mk0;
                float p1 = ex2f(sacc[m][nf][1]) * mk1;
                float p2 = ex2f(sacc[m][nf][2]) * mk0;
                float p3 = ex2f(sacc[m][nf][3]) * mk1;
                sacc[m][nf][0] = p0; sacc[m][nf][1] = p1;
                sacc[m][nf][2] = p2; sacc[m][nf][3] = p3;
                rs[m][0] += p0 + p1;
                rs[m][1] += p2 + p3;
            }
        }
        #pragma unroll
        for (int m = 0; m < 2; m++) {
            #pragma unroll
            for (int h = 0; h < 2; h++) {
                float v = rs[m][h];
                v += __shfl_xor_sync(0xffffffffu, v, 1);
                v += __shfl_xor_sync(0xffffffffu, v, 2);
                rs[m][h] = v;
            }
            if (tg == 0) {
                lsum[warp_n * 128 + r0 + m * 16 + g] = rs[m][0];
                lsum[warp_n * 128 + r0 + m * 16 + 8 + g] = rs[m][1];
            }
        }
        __syncthreads();
        if (tid < 128) ltot[tid] += lsum[tid] + lsum[128 + tid];

        // ---- O += P V  (P fragments packed straight from sacc) ----
        #pragma unroll
        for (int s = 0; s < 4; s++) {
            uint32_t pa0[4], pa1[4];
            pa0[0] = packh2(sacc[0][2 * s][0],     sacc[0][2 * s][1]);
            pa0[1] = packh2(sacc[0][2 * s][2],     sacc[0][2 * s][3]);
            pa0[2] = packh2(sacc[0][2 * s + 1][0], sacc[0][2 * s + 1][1]);
            pa0[3] = packh2(sacc[0][2 * s + 1][2], sacc[0][2 * s + 1][3]);
            pa1[0] = packh2(sacc[1][2 * s][0],     sacc[1][2 * s][1]);
            pa1[1] = packh2(sacc[1][2 * s][2],     sacc[1][2 * s][3]);
            pa1[2] = packh2(sacc[1][2 * s + 1][0], sacc[1][2 * s + 1][1]);
            pa1[3] = packh2(sacc[1][2 * s + 1][2], sacc[1][2 * s + 1][3]);
            #pragma unroll
            for (int nf = 0; nf < 8; nf++) {
                uint32_t b0, b1;
                uint32_t a = vb_base +
                    ((uint32_t)((n0 + 16 * s + (lane & 15)) * KV_STRH + nf * 8)) * 2u;
                ldmx2t(b0, b1, a);
                mma16(oacc[0][nf], pa0, b0, b1);
                mma16(oacc[1][nf], pa1, b0, b1);
            }
        }
        __syncthreads();   // protect Ks/Vs before next tile
    }

    // ---- combine warp_n halves through SMEM, normalize, store ----
    if (warp_n == 0) {
        #pragma unroll
        for (int m = 0; m < 2; m++)
            #pragma unroll
            for (int nf = 0; nf < 8; nf++) {
                int r = r0 + m * 16 + g, c = nf * 8 + 2 * tg;
                *(float2*)&Obuf[r * OB_STR + c] =
                    make_float2(oacc[m][nf][0], oacc[m][nf][1]);
                *(float2*)&Obuf[(r + 8) * OB_STR + c] =
                    make_float2(oacc[m][nf][2], oacc[m][nf][3]);
            }
    }
    __syncthreads();
    if (warp_n == 1) {
        #pragma unroll
        for (int m = 0; m < 2; m++)
            #pragma unroll
            for (int nf = 0; nf < 8; nf++) {
                int r = r0 + m * 16 + g, c = nf * 8 + 2 * tg;
                float2 t0 = *(float2*)&Obuf[r * OB_STR + c];
                float2 t1 = *(float2*)&Obuf[(r + 8) * OB_STR + c];
                t0.x += oacc[m][nf][0]; t0.y += oacc[m][nf][1];
                t1.x += oacc[m][nf][2]; t1.y += oacc[m][nf][3];
                *(float2*)&Obuf[r * OB_STR + c] = t0;
                *(float2*)&Obuf[(r + 8) * OB_STR + c] = t1;
            }
    }
    __syncthreads();

    #pragma unroll
    for (int i = 0; i < 8; i++) {
        int idx = tid + i * 256;
        int r = idx >> 4, d4 = (idx & 15) * 4;
        float inv = 1.f / ltot[r];
        float4 v;
        v.x = Obuf[r * OB_STR + d4 + 0] * inv;
        v.y = Obuf[r * OB_STR + d4 + 1] * inv;
        v.z = Obuf[r * OB_STR + d4 + 2] * inv;
        v.w = Obuf[r * OB_STR + d4 + 3] * inv;
        *(float4*)&out[(size_t)(b * SS + q0 + r) * DH + d4] = v;
    }
}

// ===========================================================================
extern "C" void kernel_launch(void* const* d_in, const int* in_sizes, int n_in,
                              void* d_out, int out_size)
{
    const float* x  = (const float*)d_in[0];
    const int* mask = (const int*)d_in[1];
    const float* Wq = (const float*)d_in[2];
    const float* bq = (const float*)d_in[3];
    const float* Wk = (const float*)d_in[4];
    const float* bk = (const float*)d_in[5];
    const float* Wv = (const float*)d_in[6];
    const float* bv = (const float*)d_in[7];
    float* out = (float*)d_out;

    qkv_mma<<<BB * SS / 128, 256>>>(x, Wq, bq, Wk, bk, Wv, bv);

    const int smem = 36864 + (128 + 256 + 128) * (int)sizeof(float);   // 38912
    cudaFuncSetAttribute(attn_mma, cudaFuncAttributeMaxDynamicSharedMemorySize, smem);
    dim3 g2(SS / QT, BB);
    attn_mma<<<g2, 256, smem>>>(mask, out);
}

// round 5
// speedup vs baseline: 7.5818x; 1.1270x over previous
#include <cuda_runtime.h>
#include <cuda_fp16.h>
#include <cstdint>

#define BB 4
#define SS 4096
#define DE 768
#define DH 64
#define QT 128
#define KT 128

// fp16 scratch for projected Q (pre-scaled), K, V.
__device__ __half g_qh[BB * SS * DH];
__device__ __half g_kh[BB * SS * DH];
__device__ __half g_vh[BB * SS * DH];

// ---------------------------------------------------------------------------
// helpers
// ---------------------------------------------------------------------------
__device__ __forceinline__ uint32_t f2tf32(float x) {
    uint32_t r;
    asm("cvt.rna.tf32.f32 %0, %1;" : "=r"(r) : "f"(x));
    return r;
}
__device__ __forceinline__ float ex2f(float x) {
    float y; asm("ex2.approx.f32 %0, %1;" : "=f"(y) : "f"(x)); return y;
}
__device__ __forceinline__ void mma8(float* d, const uint32_t* a, const uint32_t* b) {
    asm volatile(
        "mma.sync.aligned.m16n8k8.row.col.f32.tf32.tf32.f32 "
        "{%0,%1,%2,%3}, {%4,%5,%6,%7}, {%8,%9}, {%0,%1,%2,%3};"
        : "+f"(d[0]), "+f"(d[1]), "+f"(d[2]), "+f"(d[3])
        : "r"(a[0]), "r"(a[1]), "r"(a[2]), "r"(a[3]), "r"(b[0]), "r"(b[1]));
}
__device__ __forceinline__ void mma16(float* d, const uint32_t* a, uint32_t b0, uint32_t b1) {
    asm volatile(
        "mma.sync.aligned.m16n8k16.row.col.f32.f16.f16.f32 "
        "{%0,%1,%2,%3}, {%4,%5,%6,%7}, {%8,%9}, {%0,%1,%2,%3};"
        : "+f"(d[0]), "+f"(d[1]), "+f"(d[2]), "+f"(d[3])
        : "r"(a[0]), "r"(a[1]), "r"(a[2]), "r"(a[3]), "r"(b0), "r"(b1));
}
__device__ __forceinline__ void ldmx4(uint32_t* r, uint32_t addr) {
    asm volatile("ldmatrix.sync.aligned.m8n8.x4.shared.b16 {%0,%1,%2,%3}, [%4];"
        : "=r"(r[0]), "=r"(r[1]), "=r"(r[2]), "=r"(r[3]) : "r"(addr));
}
__device__ __forceinline__ void ldmx2(uint32_t& r0, uint32_t& r1, uint32_t addr) {
    asm volatile("ldmatrix.sync.aligned.m8n8.x2.shared.b16 {%0,%1}, [%2];"
        : "=r"(r0), "=r"(r1) : "r"(addr));
}
__device__ __forceinline__ void ldmx2t(uint32_t& r0, uint32_t& r1, uint32_t addr) {
    asm volatile("ldmatrix.sync.aligned.m8n8.x2.trans.shared.b16 {%0,%1}, [%2];"
        : "=r"(r0), "=r"(r1) : "r"(addr));
}
__device__ __forceinline__ uint32_t packh2(float lo, float hi) {
    __half2 h = __floats2half2_rn(lo, hi);
    return *(uint32_t*)&h;
}
__device__ __forceinline__ void cpasync16(uint32_t dst, const void* src) {
    asm volatile("cp.async.cg.shared.global [%0], [%1], 16;"
        :: "r"(dst), "l"(src) : "memory");
}
#define CP_COMMIT() asm volatile("cp.async.commit_group;" ::: "memory")
#define CP_WAIT0()  asm volatile("cp.async.wait_group 0;" ::: "memory")

// ===========================================================================
// Fused QKV projection via tf32 mma.sync -> fp16 outputs (Q pre-scaled).
// ===========================================================================
#define XS_STR 36
#define WS_STR 200

__global__ __launch_bounds__(256) void qkv_mma(
    const float* __restrict__ X,
    const float* __restrict__ Wq, const float* __restrict__ bq,
    const float* __restrict__ Wk, const float* __restrict__ bk,
    const float* __restrict__ Wv, const float* __restrict__ bv)
{
    __shared__ float Xs[128 * XS_STR];
    __shared__ float Ws[32 * WS_STR];
    __shared__ float bsm[192];

    const int tid = threadIdx.x;
    const int wid = tid >> 5, lane = tid & 31;
    const int g = lane >> 2, tg = lane & 3;
    const int warp_m = wid & 3, warp_n = wid >> 2;
    const int r0 = warp_m * 32;
    const int n0 = warp_n * 96;
    const int m0 = blockIdx.x * 128;

    if (tid < 192) {
        float bv_ = (tid < 64) ? bq[tid] : (tid < 128) ? bk[tid - 64] : bv[tid - 128];
        bsm[tid] = bv_;
    }

    float acc[2][12][4];
    #pragma unroll
    for (int m = 0; m < 2; m++)
        #pragma unroll
        for (int n = 0; n < 12; n++)
            #pragma unroll
            for (int i = 0; i < 4; i++) acc[m][n][i] = 0.f;

    for (int k0 = 0; k0 < DE; k0 += 32) {
        #pragma unroll
        for (int i = 0; i < 4; i++) {
            int idx = tid + i * 256;
            int r = idx >> 3, c4 = (idx & 7) * 4;
            float4 v = *(const float4*)&X[(size_t)(m0 + r) * DE + k0 + c4];
            uint4 u = make_uint4(f2tf32(v.x), f2tf32(v.y), f2tf32(v.z), f2tf32(v.w));
            *(uint4*)&Xs[r * XS_STR + c4] = u;
        }
        #pragma unroll
        for (int mtx = 0; mtx < 3; mtx++) {
            const float* W = (mtx == 0) ? Wq : (mtx == 1) ? Wk : Wv;
            #pragma unroll
            for (int i = 0; i < 2; i++) {
                int idx = tid + i * 256;
                int kr = idx >> 4, c4 = (idx & 15) * 4;
                float4 v = *(const float4*)&W[(size_t)(k0 + kr) * DH + c4];
                uint4 u = make_uint4(f2tf32(v.x), f2tf32(v.y), f2tf32(v.z), f2tf32(v.w));
                *(uint4*)&Ws[kr * WS_STR + mtx * 64 + c4] = u;
            }
        }
        __syncthreads();

        #pragma unroll
        for (int kf = 0; kf < 4; kf++) {
            uint32_t a[2][4];
            #pragma unroll
            for (int m = 0; m < 2; m++) {
                int r = r0 + m * 16 + g;
                a[m][0] = __float_as_uint(Xs[r * XS_STR + kf * 8 + tg]);
                a[m][1] = __float_as_uint(Xs[(r + 8) * XS_STR + kf * 8 + tg]);
                a[m][2] = __float_as_uint(Xs[r * XS_STR + kf * 8 + tg + 4]);
                a[m][3] = __float_as_uint(Xs[(r + 8) * XS_STR + kf * 8 + tg + 4]);
            }
            #pragma unroll
            for (int nf = 0; nf < 12; nf++) {
                uint32_t b[2];
                b[0] = __float_as_uint(Ws[(kf * 8 + tg) * WS_STR + n0 + nf * 8 + g]);
                b[1] = __float_as_uint(Ws[(kf * 8 + tg + 4) * WS_STR + n0 + nf * 8 + g]);
                mma8(acc[0][nf], a[0], b);
                mma8(acc[1][nf], a[1], b);
            }
        }
        __syncthreads();
    }

    const float SCL = 0.18033688011112042f;   // log2(e)/sqrt(64)
    #pragma unroll
    for (int m = 0; m < 2; m++) {
        #pragma unroll
        for (int nf = 0; nf < 12; nf++) {
            int col = n0 + nf * 8 + 2 * tg;
            int mtx = col >> 6, cc = col & 63;
            __half* C = (mtx == 0) ? g_qh : (mtx == 1) ? g_kh : g_vh;
            float s = (mtx == 0) ? SCL : 1.f;
            float b0 = bsm[col], b1 = bsm[col + 1];
            int ra = m0 + r0 + m * 16 + g;
            uint32_t u0 = packh2((acc[m][nf][0] + b0) * s, (acc[m][nf][1] + b1) * s);
            uint32_t u1 = packh2((acc[m][nf][2] + b0) * s, (acc[m][nf][3] + b1) * s);
            *(uint32_t*)&C[(size_t)ra * DH + cc] = u0;
            *(uint32_t*)&C[(size_t)(ra + 8) * DH + cc] = u1;
        }
    }
}

// ===========================================================================
// Attention: fp16 mma + ldmatrix + cp.async double-buffered pipeline.
// grid (SS/128, BB), 256 threads = 8 warps (warp_m rows/32, warp_n keys/64)
// ===========================================================================
#define KV_STRH 72
#define OB_STR 72

__global__ __launch_bounds__(256, 1) void attn_mma(const int* __restrict__ mask,
                                                   float* __restrict__ out)
{
    extern __shared__ char smc[];
    // layout: Ks[2] (36864) | Vs[2] (36864) | msks[2][128] int (1024) | lsum[256] f32 (1024)
    __half* KsA[2] = { (__half*)smc, (__half*)(smc + 18432) };
    __half* VsA[2] = { (__half*)(smc + 36864), (__half*)(smc + 55296) };
    int*   msks   = (int*)(smc + 73728);
    float* lsum   = (float*)(smc + 74752);
    float* Obuf   = (float*)smc;               // reused after loop (36864 B)
    __half* Qstg  = VsA[1];                    // Q staging before pipeline warms

    const int tid = threadIdx.x;
    const int wid = tid >> 5, lane = tid & 31;
    const int g = lane >> 2, tg = lane & 3;
    const int warp_m = wid & 3, warp_n = wid >> 2;
    const int r0 = warp_m * 32;
    const int n0 = warp_n * 64;
    const int b = blockIdx.y;
    const int q0 = blockIdx.x * QT;

    const uint32_t ks_b[2] = { (uint32_t)__cvta_generic_to_shared(KsA[0]),
                               (uint32_t)__cvta_generic_to_shared(KsA[1]) };
    const uint32_t vs_b[2] = { (uint32_t)__cvta_generic_to_shared(VsA[0]),
                               (uint32_t)__cvta_generic_to_shared(VsA[1]) };

    // ---- stage Q (already fp16 + scaled in gmem) ----
    #pragma unroll
    for (int i = 0; i < 4; i++) {
        int idx = tid + i * 256;
        int r = idx >> 3, c = idx & 7;
        uint4 v = *(const uint4*)&g_qh[(size_t)(b * SS + q0 + r) * DH + c * 8];
        *(uint4*)&Qstg[r * KV_STRH + c * 8] = v;
    }
    __syncthreads();

    uint32_t qa[2][4][4];
    {
        uint32_t qbase = vs_b[1];
        #pragma unroll
        for (int m = 0; m < 2; m++)
            #pragma unroll
            for (int s = 0; s < 4; s++) {
                uint32_t a = qbase +
                    ((uint32_t)((r0 + m * 16 + (lane & 15)) * KV_STRH + 16 * s + ((lane >> 4) * 8))) * 2u;
                ldmx4(qa[m][s], a);
            }
    }
    __syncthreads();   // everyone done reading Qstg (=Vs[1]) before any prefetch hits it

    // ---- prefetch tile 0 ----
    {
        const int k0 = 0, p = 0;
        #pragma unroll
        for (int i = 0; i < 4; i++) {
            int idx = tid + i * 256;
            int r = idx >> 3, c = idx & 7;
            uint32_t off = ((uint32_t)(r * KV_STRH + c * 8)) * 2u;
            cpasync16(ks_b[p] + off, &g_kh[(size_t)(b * SS + k0 + r) * DH + c * 8]);
            cpasync16(vs_b[p] + off, &g_vh[(size_t)(b * SS + k0 + r) * DH + c * 8]);
        }
        if (tid < 32)
            cpasync16((uint32_t)__cvta_generic_to_shared(&msks[p * 128 + tid * 4]),
                      &mask[b * SS + k0 + tid * 4]);
        CP_COMMIT();
    }

    float oacc[2][8][4];
    #pragma unroll
    for (int m = 0; m < 2; m++)
        #pragma unroll
        for (int n = 0; n < 8; n++)
            #pragma unroll
            for (int i = 0; i < 4; i++) oacc[m][n][i] = 0.f;
    float rs_acc[2][2] = {{0.f, 0.f}, {0.f, 0.f}};

    for (int kt = 0; kt < SS / KT; kt++) {
        const int p = kt & 1;
        CP_WAIT0();
        __syncthreads();   // tile kt visible to all; all threads past compute kt-1

        // prefetch kt+1 into the other buffer (overlaps compute below)
        if (kt + 1 < SS / KT) {
            const int k1 = (kt + 1) * KT, p1 = p ^ 1;
            #pragma unroll
            for (int i = 0; i < 4; i++) {
                int idx = tid + i * 256;
                int r = idx >> 3, c = idx & 7;
                uint32_t off = ((uint32_t)(r * KV_STRH + c * 8)) * 2u;
                cpasync16(ks_b[p1] + off, &g_kh[(size_t)(b * SS + k1 + r) * DH + c * 8]);
                cpasync16(vs_b[p1] + off, &g_vh[(size_t)(b * SS + k1 + r) * DH + c * 8]);
            }
            if (tid < 32)
                cpasync16((uint32_t)__cvta_generic_to_shared(&msks[p1 * 128 + tid * 4]),
                          &mask[b * SS + k1 + tid * 4]);
            CP_COMMIT();
        }

        // ---- S = Q K^T ----
        float sacc[2][8][4];
        #pragma unroll
        for (int m = 0; m < 2; m++)
            #pragma unroll
            for (int n = 0; n < 8; n++)
                #pragma unroll
                for (int i = 0; i < 4; i++) sacc[m][n][i] = 0.f;

        #pragma unroll
        for (int s = 0; s < 4; s++) {
            #pragma unroll
            for (int nf = 0; nf < 8; nf++) {
                uint32_t b0, b1;
                uint32_t a = ks_b[p] +
                    ((uint32_t)((n0 + nf * 8 + (lane & 7)) * KV_STRH + 16 * s + (((lane >> 3) & 1) * 8))) * 2u;
                ldmx2(b0, b1, a);
                mma16(sacc[0][nf], qa[0][s], b0, b1);
                mma16(sacc[1][nf], qa[1][s], b0, b1);
            }
        }

        // ---- p = exp2(s) * mask; accumulate row sums in registers ----
        #pragma unroll
        for (int m = 0; m < 2; m++) {
            #pragma unroll
            for (int nf = 0; nf < 8; nf++) {
                int c = n0 + nf * 8 + 2 * tg;
                float mk0 = msks[p * 128 + c]     ? 1.f : 0.f;
                float mk1 = msks[p * 128 + c + 1] ? 1.f : 0.f;
                float p0 = ex2f(sacc[m][nf][0]) * mk0;
                float p1 = ex2f(sacc[m][nf][1]) * mk1;
                float p2 = ex2f(sacc[m][nf][2]) * mk0;
                float p3 = ex2f(sacc[m][nf][3]) * mk1;
                sacc[m][nf][0] = p0; sacc[m][nf][1] = p1;
                sacc[m][nf][2] = p2; sacc[m][nf][3] = p3;
                rs_acc[m][0] += p0 + p1;
                rs_acc[m][1] += p2 + p3;
            }
        }

        // ---- O += P V ----
        #pragma unroll
        for (int s = 0; s < 4; s++) {
            uint32_t pa0[4], pa1[4];
            pa0[0] = packh2(sacc[0][2 * s][0],     sacc[0][2 * s][1]);
            pa0[1] = packh2(sacc[0][2 * s][2],     sacc[0][2 * s][3]);
            pa0[2] = packh2(sacc[0][2 * s + 1][0], sacc[0][2 * s + 1][1]);
            pa0[3] = packh2(sacc[0][2 * s + 1][2], sacc[0][2 * s + 1][3]);
            pa1[0] = packh2(sacc[1][2 * s][0],     sacc[1][2 * s][1]);
            pa1[1] = packh2(sacc[1][2 * s][2],     sacc[1][2 * s][3]);
            pa1[2] = packh2(sacc[1][2 * s + 1][0], sacc[1][2 * s + 1][1]);
            pa1[3] = packh2(sacc[1][2 * s + 1][2], sacc[1][2 * s + 1][3]);
            #pragma unroll
            for (int nf = 0; nf < 8; nf++) {
                uint32_t b0, b1;
                uint32_t a = vs_b[p] +
                    ((uint32_t)((n0 + 16 * s + (lane & 15)) * KV_STRH + nf * 8)) * 2u;
                ldmx2t(b0, b1, a);
                mma16(oacc[0][nf], pa0, b0, b1);
                mma16(oacc[1][nf], pa1, b0, b1);
            }
        }
    }
    __syncthreads();   // all compute done before Obuf/lsum reuse

    // ---- final row-sum reduction (once) ----
    #pragma unroll
    for (int m = 0; m < 2; m++)
        #pragma unroll
        for (int h = 0; h < 2; h++) {
            float v = rs_acc[m][h];
            v += __shfl_xor_sync(0xffffffffu, v, 1);
            v += __shfl_xor_sync(0xffffffffu, v, 2);
            if (tg == 0) lsum[warp_n * 128 + r0 + m * 16 + h * 8 + g] = v;
        }
    __syncthreads();

    // ---- combine warp_n halves through Obuf ----
    if (warp_n == 0) {
        #pragma unroll
        for (int m = 0; m < 2; m++)
            #pragma unroll
            for (int nf = 0; nf < 8; nf++) {
                int r = r0 + m * 16 + g, c = nf * 8 + 2 * tg;
                *(float2*)&Obuf[r * OB_STR + c] =
                    make_float2(oacc[m][nf][0], oacc[m][nf][1]);
                *(float2*)&Obuf[(r + 8) * OB_STR + c] =
                    make_float2(oacc[m][nf][2], oacc[m][nf][3]);
            }
    }
    __syncthreads();
    if (warp_n == 1) {
        #pragma unroll
        for (int m = 0; m < 2; m++)
            #pragma unroll
            for (int nf = 0; nf < 8; nf++) {
                int r = r0 + m * 16 + g, c = nf * 8 + 2 * tg;
                float2 t0 = *(float2*)&Obuf[r * OB_STR + c];
                float2 t1 = *(float2*)&Obuf[(r + 8) * OB_STR + c];
                t0.x += oacc[m][nf][0]; t0.y += oacc[m][nf][1];
                t1.x += oacc[m][nf][2]; t1.y += oacc[m][nf][3];
                *(float2*)&Obuf[r * OB_STR + c] = t0;
                *(float2*)&Obuf[(r + 8) * OB_STR + c] = t1;
            }
    }
    __syncthreads();

    #pragma unroll
    for (int i = 0; i < 8; i++) {
        int idx = tid + i * 256;
        int r = idx >> 4, d4 = (idx & 15) * 4;
        float inv = 1.f / (lsum[r] + lsum[128 + r]);
        float4 v;
        v.x = Obuf[r * OB_STR + d4 + 0] * inv;
        v.y = Obuf[r * OB_STR + d4 + 1] * inv;
        v.z = Obuf[r * OB_STR + d4 + 2] * inv;
        v.w = Obuf[r * OB_STR + d4 + 3] * inv;
        *(float4*)&out[(size_t)(b * SS + q0 + r) * DH + d4] = v;
    }
}

// ===========================================================================
extern "C" void kernel_launch(void* const* d_in, const int* in_sizes, int n_in,
                              void* d_out, int out_size)
{
    const float* x  = (const float*)d_in[0];
    const int* mask = (const int*)d_in[1];
    const float* Wq = (const float*)d_in[2];
    const float* bq = (const float*)d_in[3];
    const float* Wk = (const float*)d_in[4];
    const float* bk = (const float*)d_in[5];
    const float* Wv = (const float*)d_in[6];
    const float* bv = (const float*)d_in[7];
    float* out = (float*)d_out;

    qkv_mma<<<BB * SS / 128, 256>>>(x, Wq, bq, Wk, bk, Wv, bv);

    const int smem = 75776;
    cudaFuncSetAttribute(attn_mma, cudaFuncAttributeMaxDynamicSharedMemorySize, smem);
    dim3 g2(SS / QT, BB);
    attn_mma<<<g2, 256, smem>>>(mask, out);
}

// round 6
// speedup vs baseline: 7.5839x; 1.0003x over previous
#include <cuda_runtime.h>
#include <cuda_fp16.h>
#include <cstdint>

#define BB 4
#define SS 4096
#define DE 768
#define DH 64
#define QT 128
#define KT 128

// fp16 scratch for projected Q (pre-scaled), K, V.
__device__ __half g_qh[BB * SS * DH];
__device__ __half g_kh[BB * SS * DH];
__device__ __half g_vh[BB * SS * DH];

// ---------------------------------------------------------------------------
// helpers
// ---------------------------------------------------------------------------
__device__ __forceinline__ uint32_t f2tf32(float x) {
    uint32_t r;
    asm("cvt.rna.tf32.f32 %0, %1;" : "=r"(r) : "f"(x));
    return r;
}
__device__ __forceinline__ float ex2f(float x) {
    float y; asm("ex2.approx.f32 %0, %1;" : "=f"(y) : "f"(x)); return y;
}
__device__ __forceinline__ void mma8(float* d, const uint32_t* a, const uint32_t* b) {
    asm volatile(
        "mma.sync.aligned.m16n8k8.row.col.f32.tf32.tf32.f32 "
        "{%0,%1,%2,%3}, {%4,%5,%6,%7}, {%8,%9}, {%0,%1,%2,%3};"
        : "+f"(d[0]), "+f"(d[1]), "+f"(d[2]), "+f"(d[3])
        : "r"(a[0]), "r"(a[1]), "r"(a[2]), "r"(a[3]), "r"(b[0]), "r"(b[1]));
}
__device__ __forceinline__ void mma16(float* d, const uint32_t* a, uint32_t b0, uint32_t b1) {
    asm volatile(
        "mma.sync.aligned.m16n8k16.row.col.f32.f16.f16.f32 "
        "{%0,%1,%2,%3}, {%4,%5,%6,%7}, {%8,%9}, {%0,%1,%2,%3};"
        : "+f"(d[0]), "+f"(d[1]), "+f"(d[2]), "+f"(d[3])
        : "r"(a[0]), "r"(a[1]), "r"(a[2]), "r"(a[3]), "r"(b0), "r"(b1));
}
__device__ __forceinline__ void ldmx4(uint32_t* r, uint32_t addr) {
    asm volatile("ldmatrix.sync.aligned.m8n8.x4.shared.b16 {%0,%1,%2,%3}, [%4];"
        : "=r"(r[0]), "=r"(r[1]), "=r"(r[2]), "=r"(r[3]) : "r"(addr));
}
__device__ __forceinline__ void ldmx2(uint32_t& r0, uint32_t& r1, uint32_t addr) {
    asm volatile("ldmatrix.sync.aligned.m8n8.x2.shared.b16 {%0,%1}, [%2];"
        : "=r"(r0), "=r"(r1) : "r"(addr));
}
__device__ __forceinline__ void ldmx2t(uint32_t& r0, uint32_t& r1, uint32_t addr) {
    asm volatile("ldmatrix.sync.aligned.m8n8.x2.trans.shared.b16 {%0,%1}, [%2];"
        : "=r"(r0), "=r"(r1) : "r"(addr));
}
__device__ __forceinline__ uint32_t packh2(float lo, float hi) {
    __half2 h = __floats2half2_rn(lo, hi);
    return *(uint32_t*)&h;
}
__device__ __forceinline__ void cpasync16(uint32_t dst, const void* src) {
    asm volatile("cp.async.cg.shared.global [%0], [%1], 16;"
        :: "r"(dst), "l"(src) : "memory");
}
#define CP_COMMIT() asm volatile("cp.async.commit_group;" ::: "memory")
#define CP_WAIT0()  asm volatile("cp.async.wait_group 0;" ::: "memory")

// ===========================================================================
// Fused QKV projection via tf32 mma.sync -> fp16 outputs (Q pre-scaled).
// ===========================================================================
#define XS_STR 36
#define WS_STR 200

__global__ __launch_bounds__(256) void qkv_mma(
    const float* __restrict__ X,
    const float* __restrict__ Wq, const float* __restrict__ bq,
    const float* __restrict__ Wk, const float* __restrict__ bk,
    const float* __restrict__ Wv, const float* __restrict__ bv)
{
    __shared__ float Xs[128 * XS_STR];
    __shared__ float Ws[32 * WS_STR];
    __shared__ float bsm[192];

    const int tid = threadIdx.x;
    const int wid = tid >> 5, lane = tid & 31;
    const int g = lane >> 2, tg = lane & 3;
    const int warp_m = wid & 3, warp_n = wid >> 2;
    const int r0 = warp_m * 32;
    const int n0 = warp_n * 96;
    const int m0 = blockIdx.x * 128;

    if (tid < 192) {
        float bv_ = (tid < 64) ? bq[tid] : (tid < 128) ? bk[tid - 64] : bv[tid - 128];
        bsm[tid] = bv_;
    }

    float acc[2][12][4];
    #pragma unroll
    for (int m = 0; m < 2; m++)
        #pragma unroll
        for (int n = 0; n < 12; n++)
            #pragma unroll
            for (int i = 0; i < 4; i++) acc[m][n][i] = 0.f;

    for (int k0 = 0; k0 < DE; k0 += 32) {
        #pragma unroll
        for (int i = 0; i < 4; i++) {
            int idx = tid + i * 256;
            int r = idx >> 3, c4 = (idx & 7) * 4;
            float4 v = *(const float4*)&X[(size_t)(m0 + r) * DE + k0 + c4];
            uint4 u = make_uint4(f2tf32(v.x), f2tf32(v.y), f2tf32(v.z), f2tf32(v.w));
            *(uint4*)&Xs[r * XS_STR + c4] = u;
        }
        #pragma unroll
        for (int mtx = 0; mtx < 3; mtx++) {
            const float* W = (mtx == 0) ? Wq : (mtx == 1) ? Wk : Wv;
            #pragma unroll
            for (int i = 0; i < 2; i++) {
                int idx = tid + i * 256;
                int kr = idx >> 4, c4 = (idx & 15) * 4;
                float4 v = *(const float4*)&W[(size_t)(k0 + kr) * DH + c4];
                uint4 u = make_uint4(f2tf32(v.x), f2tf32(v.y), f2tf32(v.z), f2tf32(v.w));
                *(uint4*)&Ws[kr * WS_STR + mtx * 64 + c4] = u;
            }
        }
        __syncthreads();

        #pragma unroll
        for (int kf = 0; kf < 4; kf++) {
            uint32_t a[2][4];
            #pragma unroll
            for (int m = 0; m < 2; m++) {
                int r = r0 + m * 16 + g;
                a[m][0] = __float_as_uint(Xs[r * XS_STR + kf * 8 + tg]);
                a[m][1] = __float_as_uint(Xs[(r + 8) * XS_STR + kf * 8 + tg]);
                a[m][2] = __float_as_uint(Xs[r * XS_STR + kf * 8 + tg + 4]);
                a[m][3] = __float_as_uint(Xs[(r + 8) * XS_STR + kf * 8 + tg + 4]);
            }
            #pragma unroll
            for (int nf = 0; nf < 12; nf++) {
                uint32_t b[2];
                b[0] = __float_as_uint(Ws[(kf * 8 + tg) * WS_STR + n0 + nf * 8 + g]);
                b[1] = __float_as_uint(Ws[(kf * 8 + tg + 4) * WS_STR + n0 + nf * 8 + g]);
                mma8(acc[0][nf], a[0], b);
                mma8(acc[1][nf], a[1], b);
            }
        }
        __syncthreads();
    }

    const float SCL = 0.18033688011112042f;   // log2(e)/sqrt(64)
    #pragma unroll
    for (int m = 0; m < 2; m++) {
        #pragma unroll
        for (int nf = 0; nf < 12; nf++) {
            int col = n0 + nf * 8 + 2 * tg;
            int mtx = col >> 6, cc = col & 63;
            __half* C = (mtx == 0) ? g_qh : (mtx == 1) ? g_kh : g_vh;
            float s = (mtx == 0) ? SCL : 1.f;
            float b0 = bsm[col], b1 = bsm[col + 1];
            int ra = m0 + r0 + m * 16 + g;
            uint32_t u0 = packh2((acc[m][nf][0] + b0) * s, (acc[m][nf][1] + b1) * s);
            uint32_t u1 = packh2((acc[m][nf][2] + b0) * s, (acc[m][nf][3] + b1) * s);
            *(uint32_t*)&C[(size_t)ra * DH + cc] = u0;
            *(uint32_t*)&C[(size_t)(ra + 8) * DH + cc] = u1;
        }
    }
}

// ===========================================================================
// Attention: fp16 mma + ldmatrix + cp.async double-buffered pipeline.
// grid (SS/128, BB), 256 threads = 8 warps (warp_m rows/32, warp_n keys/64)
// ===========================================================================
#define KV_STRH 72
#define OB_STR 72

__global__ __launch_bounds__(256, 1) void attn_mma(const int* __restrict__ mask,
                                                   float* __restrict__ out)
{
    extern __shared__ char smc[];
    // layout: Ks[2] (36864) | Vs[2] (36864) | msks[2][128] int (1024) | lsum[256] f32 (1024)
    __half* KsA[2] = { (__half*)smc, (__half*)(smc + 18432) };
    __half* VsA[2] = { (__half*)(smc + 36864), (__half*)(smc + 55296) };
    int*   msks   = (int*)(smc + 73728);
    float* lsum   = (float*)(smc + 74752);
    float* Obuf   = (float*)smc;               // reused after loop (36864 B)
    __half* Qstg  = VsA[1];                    // Q staging before pipeline warms

    const int tid = threadIdx.x;
    const int wid = tid >> 5, lane = tid & 31;
    const int g = lane >> 2, tg = lane & 3;
    const int warp_m = wid & 3, warp_n = wid >> 2;
    const int r0 = warp_m * 32;
    const int n0 = warp_n * 64;
    const int b = blockIdx.y;
    const int q0 = blockIdx.x * QT;

    const uint32_t ks_b[2] = { (uint32_t)__cvta_generic_to_shared(KsA[0]),
                               (uint32_t)__cvta_generic_to_shared(KsA[1]) };
    const uint32_t vs_b[2] = { (uint32_t)__cvta_generic_to_shared(VsA[0]),
                               (uint32_t)__cvta_generic_to_shared(VsA[1]) };

    // ---- stage Q (already fp16 + scaled in gmem) ----
    #pragma unroll
    for (int i = 0; i < 4; i++) {
        int idx = tid + i * 256;
        int r = idx >> 3, c = idx & 7;
        uint4 v = *(const uint4*)&g_qh[(size_t)(b * SS + q0 + r) * DH + c * 8];
        *(uint4*)&Qstg[r * KV_STRH + c * 8] = v;
    }
    __syncthreads();

    uint32_t qa[2][4][4];
    {
        uint32_t qbase = vs_b[1];
        #pragma unroll
        for (int m = 0; m < 2; m++)
            #pragma unroll
            for (int s = 0; s < 4; s++) {
                uint32_t a = qbase +
                    ((uint32_t)((r0 + m * 16 + (lane & 15)) * KV_STRH + 16 * s + ((lane >> 4) * 8))) * 2u;
                ldmx4(qa[m][s], a);
            }
    }
    __syncthreads();   // everyone done reading Qstg (=Vs[1]) before any prefetch hits it

    // ---- prefetch tile 0 ----
    {
        const int k0 = 0, p = 0;
        #pragma unroll
        for (int i = 0; i < 4; i++) {
            int idx = tid + i * 256;
            int r = idx >> 3, c = idx & 7;
            uint32_t off = ((uint32_t)(r * KV_STRH + c * 8)) * 2u;
            cpasync16(ks_b[p] + off, &g_kh[(size_t)(b * SS + k0 + r) * DH + c * 8]);
            cpasync16(vs_b[p] + off, &g_vh[(size_t)(b * SS + k0 + r) * DH + c * 8]);
        }
        if (tid < 32)
            cpasync16((uint32_t)__cvta_generic_to_shared(&msks[p * 128 + tid * 4]),
                      &mask[b * SS + k0 + tid * 4]);
        CP_COMMIT();
    }

    float oacc[2][8][4];
    #pragma unroll
    for (int m = 0; m < 2; m++)
        #pragma unroll
        for (int n = 0; n < 8; n++)
            #pragma unroll
            for (int i = 0; i < 4; i++) oacc[m][n][i] = 0.f;
    float rs_acc[2][2] = {{0.f, 0.f}, {0.f, 0.f}};

    for (int kt = 0; kt < SS / KT; kt++) {
        const int p = kt & 1;
        CP_WAIT0();
        __syncthreads();   // tile kt visible to all; all threads past compute kt-1

        // prefetch kt+1 into the other buffer (overlaps compute below)
        if (kt + 1 < SS / KT) {
            const int k1 = (kt + 1) * KT, p1 = p ^ 1;
            #pragma unroll
            for (int i = 0; i < 4; i++) {
                int idx = tid + i * 256;
                int r = idx >> 3, c = idx & 7;
                uint32_t off = ((uint32_t)(r * KV_STRH + c * 8)) * 2u;
                cpasync16(ks_b[p1] + off, &g_kh[(size_t)(b * SS + k1 + r) * DH + c * 8]);
                cpasync16(vs_b[p1] + off, &g_vh[(size_t)(b * SS + k1 + r) * DH + c * 8]);
            }
            if (tid < 32)
                cpasync16((uint32_t)__cvta_generic_to_shared(&msks[p1 * 128 + tid * 4]),
                          &mask[b * SS + k1 + tid * 4]);
            CP_COMMIT();
        }

        // ---- S = Q K^T ----
        float sacc[2][8][4];
        #pragma unroll
        for (int m = 0; m < 2; m++)
            #pragma unroll
            for (int n = 0; n < 8; n++)
                #pragma unroll
                for (int i = 0; i < 4; i++) sacc[m][n][i] = 0.f;

        #pragma unroll
        for (int s = 0; s < 4; s++) {
            #pragma unroll
            for (int nf = 0; nf < 8; nf++) {
                uint32_t b0, b1;
                uint32_t a = ks_b[p] +
                    ((uint32_t)((n0 + nf * 8 + (lane & 7)) * KV_STRH + 16 * s + (((lane >> 3) & 1) * 8))) * 2u;
                ldmx2(b0, b1, a);
                mma16(sacc[0][nf], qa[0][s], b0, b1);
                mma16(sacc[1][nf], qa[1][s], b0, b1);
            }
        }

        // ---- p = exp2(s) * mask; accumulate row sums in registers ----
        #pragma unroll
        for (int m = 0; m < 2; m++) {
            #pragma unroll
            for (int nf = 0; nf < 8; nf++) {
                int c = n0 + nf * 8 + 2 * tg;
                float mk0 = msks[p * 128 + c]     ? 1.f : 0.f;
                float mk1 = msks[p * 128 + c + 1] ? 1.f : 0.f;
                float p0 = ex2f(sacc[m][nf][0]) * mk0;
                float p1 = ex2f(sacc[m][nf][1]) * mk1;
                float p2 = ex2f(sacc[m][nf][2]) * mk0;
                float p3 = ex2f(sacc[m][nf][3]) * mk1;
                sacc[m][nf][0] = p0; sacc[m][nf][1] = p1;
                sacc[m][nf][2] = p2; sacc[m][nf][3] = p3;
                rs_acc[m][0] += p0 + p1;
                rs_acc[m][1] += p2 + p3;
            }
        }

        // ---- O += P V ----
        #pragma unroll
        for (int s = 0; s < 4; s++) {
            uint32_t pa0[4], pa1[4];
            pa0[0] = packh2(sacc[0][2 * s][0],     sacc[0][2 * s][1]);
            pa0[1] = packh2(sacc[0][2 * s][2],     sacc[0][2 * s][3]);
            pa0[2] = packh2(sacc[0][2 * s + 1][0], sacc[0][2 * s + 1][1]);
            pa0[3] = packh2(sacc[0][2 * s + 1][2], sacc[0][2 * s + 1][3]);
            pa1[0] = packh2(sacc[1][2 * s][0],     sacc[1][2 * s][1]);
            pa1[1] = packh2(sacc[1][2 * s][2],     sacc[1][2 * s][3]);
            pa1[2] = packh2(sacc[1][2 * s + 1][0], sacc[1][2 * s + 1][1]);
            pa1[3] = packh2(sacc[1][2 * s + 1][2], sacc[1][2 * s + 1][3]);
            #pragma unroll
            for (int nf = 0; nf < 8; nf++) {
                uint32_t b0, b1;
                uint32_t a = vs_b[p] +
                    ((uint32_t)((n0 + 16 * s + (lane & 15)) * KV_STRH + nf * 8)) * 2u;
                ldmx2t(b0, b1, a);
                mma16(oacc[0][nf], pa0, b0, b1);
                mma16(oacc[1][nf], pa1, b0, b1);
            }
        }
    }
    __syncthreads();   // all compute done before Obuf/lsum reuse

    // ---- final row-sum reduction (once) ----
    #pragma unroll
    for (int m = 0; m < 2; m++)
        #pragma unroll
        for (int h = 0; h < 2; h++) {
            float v = rs_acc[m][h];
            v += __shfl_xor_sync(0xffffffffu, v, 1);
            v += __shfl_xor_sync(0xffffffffu, v, 2);
            if (tg == 0) lsum[warp_n * 128 + r0 + m * 16 + h * 8 + g] = v;
        }
    __syncthreads();

    // ---- combine warp_n halves through Obuf ----
    if (warp_n == 0) {
        #pragma unroll
        for (int m = 0; m < 2; m++)
            #pragma unroll
            for (int nf = 0; nf < 8; nf++) {
                int r = r0 + m * 16 + g, c = nf * 8 + 2 * tg;
                *(float2*)&Obuf[r * OB_STR + c] =
                    make_float2(oacc[m][nf][0], oacc[m][nf][1]);
                *(float2*)&Obuf[(r + 8) * OB_STR + c] =
                    make_float2(oacc[m][nf][2], oacc[m][nf][3]);
            }
    }
    __syncthreads();
    if (warp_n == 1) {
        #pragma unroll
        for (int m = 0; m < 2; m++)
            #pragma unroll
            for (int nf = 0; nf < 8; nf++) {
                int r = r0 + m * 16 + g, c = nf * 8 + 2 * tg;
                float2 t0 = *(float2*)&Obuf[r * OB_STR + c];
                float2 t1 = *(float2*)&Obuf[(r + 8) * OB_STR + c];
                t0.x += oacc[m][nf][0]; t0.y += oacc[m][nf][1];
                t1.x += oacc[m][nf][2]; t1.y += oacc[m][nf][3];
                *(float2*)&Obuf[r * OB_STR + c] = t0;
                *(float2*)&Obuf[(r + 8) * OB_STR + c] = t1;
            }
    }
    __syncthreads();

    #pragma unroll
    for (int i = 0; i < 8; i++) {
        int idx = tid + i * 256;
        int r = idx >> 4, d4 = (idx & 15) * 4;
        float inv = 1.f / (lsum[r] + lsum[128 + r]);
        float4 v;
        v.x = Obuf[r * OB_STR + d4 + 0] * inv;
        v.y = Obuf[r * OB_STR + d4 + 1] * inv;
        v.z = Obuf[r * OB_STR + d4 + 2] * inv;
        v.w = Obuf[r * OB_STR + d4 + 3] * inv;
        *(float4*)&out[(size_t)(b * SS + q0 + r) * DH + d4] = v;
    }
}

// ===========================================================================
extern "C" void kernel_launch(void* const* d_in, const int* in_sizes, int n_in,
                              void* d_out, int out_size)
{
    const float* x  = (const float*)d_in[0];
    const int* mask = (const int*)d_in[1];
    const float* Wq = (const float*)d_in[2];
    const float* bq = (const float*)d_in[3];
    const float* Wk = (const float*)d_in[4];
    const float* bk = (const float*)d_in[5];
    const float* Wv = (const float*)d_in[6];
    const float* bv = (const float*)d_in[7];
    float* out = (float*)d_out;

    qkv_mma<<<BB * SS / 128, 256>>>(x, Wq, bq, Wk, bk, Wv, bv);

    const int smem = 75776;
    cudaFuncSetAttribute(attn_mma, cudaFuncAttributeMaxDynamicSharedMemorySize, smem);
    dim3 g2(SS / QT, BB);
    attn_mma<<<g2, 256, smem>>>(mask, out);
}